// round 4
// baseline (speedup 1.0000x reference)
#include <cuda_runtime.h>
#include <cuda_bf16.h>

#define BB 4
#define PP 512
#define KK 4
#define HH 200
#define WW 336
#define AA 14
#define PS 56
#define SCALE 0.25f
#define NTHREADS 224   /* 4 rows x 56 cols */
#define NROWITER 14    /* 56 / 4 */

typedef unsigned long long ull;

__device__ __forceinline__ ull pack2(float lo, float hi) {
    ull r; asm("mov.b64 %0,{%1,%2};" : "=l"(r) : "f"(lo), "f"(hi)); return r;
}
__device__ __forceinline__ float2 unpack2(ull v) {
    float2 r; asm("mov.b64 {%0,%1},%2;" : "=f"(r.x), "=f"(r.y) : "l"(v)); return r;
}
__device__ __forceinline__ ull fma2(ull a, ull b, ull c) {
    ull d; asm("fma.rn.f32x2 %0,%1,%2,%3;" : "=l"(d) : "l"(a), "l"(b), "l"(c)); return d;
}
__device__ __forceinline__ ull mul2(ull a, ull b) {
    ull d; asm("mul.rn.f32x2 %0,%1,%2;" : "=l"(d) : "l"(a), "l"(b)); return d;
}
__device__ __forceinline__ ull add2(ull a, ull b) {
    ull d; asm("add.rn.f32x2 %0,%1,%2;" : "=l"(d) : "l"(a), "l"(b)); return d;
}
__device__ __forceinline__ float ex2f(float x) {
    float r; asm("ex2.approx.f32 %0,%1;" : "=f"(r) : "f"(x)); return r;
}

#define LOG2E 1.4426950408889634f

// bases transposed to [B][H][W][K] as float4 (K innermost)
__device__ float4 g_basesT[BB * HH * WW];

__global__ __launch_bounds__(256)
void transpose_bases_kernel(const float* __restrict__ bases)
{
    int i = blockIdx.x * blockDim.x + threadIdx.x;   // over B*H*W
    if (i >= BB * HH * WW) return;
    int b  = i / (HH * WW);
    int yx = i - b * (HH * WW);
    const float* p = bases + (size_t)b * (KK * HH * WW) + yx;
    g_basesT[i] = make_float4(p[0], p[HH * WW], p[2 * HH * WW], p[3 * HH * WW]);
}

__global__ __launch_bounds__(NTHREADS, 6)
void Blender_38809324486930_kernel(const float* __restrict__ boxes,
                                   const float* __restrict__ attn,
                                   float* __restrict__ out)
{
    const int bp = blockIdx.x;           // 0 .. B*P-1
    const int b  = bp >> 9;              // P = 512

    __shared__ float s_attnT[AA * AA * KK];      // [ay][ax][k], pre-scaled by log2e
    __shared__ float s_rowv[PS * AA * KK];       // [oy][j][k]

    const int tid = threadIdx.x;
    const int ox  = tid % PS;            // fixed column per thread
    const int r0  = tid / PS;            // starting row (0..3)

    // ---- load attention tile transposed to [ay][ax][k], scaled by log2e ----
    {
        const float* ap = attn + (size_t)bp * (KK * AA * AA);
        for (int i = tid; i < KK * AA * AA; i += NTHREADS) {
            int k  = i / (AA * AA);
            int yx = i - k * (AA * AA);
            s_attnT[yx * KK + k] = ap[i] * LOG2E;
        }
    }

    // ---- box (broadcast loads) ----
    const float bx1 = __ldg(&boxes[bp * 4 + 0]) * SCALE;
    const float by1 = __ldg(&boxes[bp * 4 + 1]) * SCALE;
    const float bx2 = __ldg(&boxes[bp * 4 + 2]) * SCALE;
    const float by2 = __ldg(&boxes[bp * 4 + 3]) * SCALE;
    const float bw = fmaxf(bx2 - bx1, 1.0f) * (1.0f / PS);
    const float bh = fmaxf(by2 - by1, 1.0f) * (1.0f / PS);

    const float resize_step = (float)(AA - 1) / (float)(PS - 1);

    // ---- per-thread x state (registers, computed once) ----
    const float sx = bx1 + ((float)ox + 0.5f) * bw;
    const float vx = (sx > -1.0f && sx < (float)WW) ? 1.0f : 0.0f;
    const float xc = fminf(fmaxf(sx, 0.0f), (float)(WW - 1));
    const int   x0 = (int)floorf(xc);
    const int   x1 = min(x0 + 1, WW - 1);
    const float lx = xc - (float)x0;

    const float srcx = (float)ox * resize_step;
    int ax0 = min(max((int)floorf(srcx), 0), AA - 2);
    const float txf = srcx - (float)ax0;
    const int axk = ax0 * KK;

    // hoisted packed constants
    const ull LXp  = pack2(lx, lx);
    const ull TXp  = pack2(txf, txf);
    const ull NEG1 = pack2(-1.0f, -1.0f);
    const ull ONEp = pack2(1.0f, 1.0f);

    __syncthreads();

    // ---- precompute row-interpolated attention: rowv[oy][j][k] ----
    for (int e = tid; e < PS * AA; e += NTHREADS) {
        const int oy = e / AA;
        const int j  = e - oy * AA;
        const float srcy = (float)oy * resize_step;
        const int ay0 = min(max((int)floorf(srcy), 0), AA - 2);
        const float ty = srcy - (float)ay0;
        const float4 a0 = *(const float4*)&s_attnT[(ay0 * AA + j) * KK];
        const float4 a1 = *(const float4*)&s_attnT[((ay0 + 1) * AA + j) * KK];
        float4 rr;
        rr.x = a0.x + ty * (a1.x - a0.x);
        rr.y = a0.y + ty * (a1.y - a0.y);
        rr.z = a0.z + ty * (a1.z - a0.z);
        rr.w = a0.w + ty * (a1.w - a0.w);
        *(float4*)&s_rowv[e * KK] = rr;
    }
    __syncthreads();

    const ulonglong2* __restrict__ fb2 =
        (const ulonglong2*)(g_basesT + (size_t)b * (HH * WW));
    const ulonglong2* __restrict__ rowv2 = (const ulonglong2*)s_rowv;
    float* ob = out + (size_t)bp * (PS * PS) + tid;

    #pragma unroll
    for (int it = 0; it < NROWITER; it++) {
        const int oy = r0 + it * 4;

        // ---- per-row y state ----
        const float sy = fmaf((float)oy + 0.5f, bh, by1);
        const float vy = (sy > -1.0f && sy < (float)HH) ? 1.0f : 0.0f;
        const float yc = fminf(fmaxf(sy, 0.0f), (float)(HH - 1));
        const int   y0 = (int)floorf(yc);
        const float ly = yc - (float)y0;
        const int y0o = y0 * WW;
        const int y1o = min(y0 + 1, HH - 1) * WW;

        // packed weights: w11=ly*lx, w10=ly-w11, w01=lx-w11, w00=1-ly-lx+w11
        const ull LYp = pack2(ly, ly);
        const ull w11 = mul2(LYp, LXp);
        const ull w10 = fma2(w11, NEG1, LYp);
        const ull w01 = fma2(w11, NEG1, LXp);
        const ull w00 = fma2(add2(LYp, LXp), NEG1, add2(ONEp, w11));
        const float vm = vy * vx;
        const ull VMp = pack2(vm, vm);

        // ---- RoIAlign taps (each 16B = 2 packed pairs) ----
        const ulonglong2 f00 = fb2[y0o + x0];
        const ulonglong2 f01 = fb2[y0o + x1];
        const ulonglong2 f10 = fb2[y1o + x0];
        const ulonglong2 f11 = fb2[y1o + x1];

        ull rlo = mul2(f00.x, w00);
        rlo = fma2(f01.x, w01, rlo);
        rlo = fma2(f10.x, w10, rlo);
        rlo = fma2(f11.x, w11, rlo);
        rlo = mul2(rlo, VMp);
        ull rhi = mul2(f00.y, w00);
        rhi = fma2(f01.y, w01, rhi);
        rhi = fma2(f10.y, w10, rhi);
        rhi = fma2(f11.y, w11, rhi);
        rhi = mul2(rhi, VMp);

        // ---- attention column lerp (packed) ----
        const int rb = (oy * AA * KK + axk) >> 2;   // index in 16B units
        const ulonglong2 a0 = rowv2[rb];
        const ulonglong2 a1 = rowv2[rb + 1];
        const ull dlo = fma2(a0.x, NEG1, a1.x);
        const ull dhi = fma2(a0.y, NEG1, a1.y);
        const ull alo = fma2(TXp, dlo, a0.x);
        const ull ahi = fma2(TXp, dhi, a0.y);

        const float2 aL = unpack2(alo);   // (a0k, a1k) in log2 units
        const float2 aH = unpack2(ahi);   // (a2k, a3k)
        const float2 rL = unpack2(rlo);
        const float2 rH = unpack2(rhi);

        // ---- softmax-blend (pivot on aL.x; 3 ex2) ----
        const float e1 = ex2f(aL.y - aL.x);
        const float e2 = ex2f(aH.x - aL.x);
        const float e3 = ex2f(aH.y - aL.x);
        const float se  = 1.0f + e1 + e2 + e3;
        float acc = rL.x;
        acc = fmaf(e1, rL.y, acc);
        acc = fmaf(e2, rH.x, acc);
        acc = fmaf(e3, rH.y, acc);
        ob[it * NTHREADS] = __fdividef(acc, se);
    }
}

extern "C" void kernel_launch(void* const* d_in, const int* in_sizes, int n_in,
                              void* d_out, int out_size)
{
    const float* bases = (const float*)d_in[0];
    const float* boxes = (const float*)d_in[1];
    const float* attn  = (const float*)d_in[2];
    float* out = (float*)d_out;

    const int nT = BB * HH * WW;
    transpose_bases_kernel<<<(nT + 255) / 256, 256>>>(bases);
    Blender_38809324486930_kernel<<<BB * PP, NTHREADS>>>(boxes, attn, out);
}